// round 10
// baseline (speedup 1.0000x reference)
#include <cuda_runtime.h>
#include <cuda_fp16.h>
#include <math.h>

#define NN 100000
#define EE 1600000
#define MM (EE + NN)
#define DD 128

struct __align__(8) Edge { int s; float w; };

// ---------------- scratch (static device allocations; no runtime alloc) ----
__device__ int   g_deg[NN];
__device__ float g_sumw[NN];
__device__ float g_loopw[NN];
__device__ int   g_rowptr[NN + 1];
__device__ int   g_wp[NN];
__device__ int   g_bsum[128];
__device__ Edge  g_edge[MM];
__device__ float g_as[NN];
__device__ float g_ad[NN];
__device__ __align__(16) __half2 g_Hh[(size_t)NN * (DD / 2)];  // fp16 H, 25.6 MB
__device__ __align__(16) float   g_ACT[(size_t)NN * DD];
__device__ float g_ce[2];

// ---------------- preprocessing ----------------
__global__ void k_init() {
    int i = blockIdx.x * blockDim.x + threadIdx.x;
    if (i < NN) { g_deg[i] = 0; g_sumw[i] = 0.f; }
}

// edge_index is int32
__global__ void k_deg(const int* __restrict__ ei, const float* __restrict__ ew) {
    int i = blockIdx.x * blockDim.x + threadIdx.x;
    if (i < EE) {
        int d = ei[EE + i];
        atomicAdd(&g_deg[d], 1);
        atomicAdd(&g_sumw[d], ew[i]);
    }
}

__global__ void k_scan1() {
    __shared__ int s[1024];
    int i = blockIdx.x * 1024 + threadIdx.x;
    int v = (i < NN) ? g_deg[i] + 1 : 0;   // +1 self-loop
    s[threadIdx.x] = v;
    __syncthreads();
    for (int off = 1; off < 1024; off <<= 1) {
        int t = (threadIdx.x >= off) ? s[threadIdx.x - off] : 0;
        __syncthreads();
        s[threadIdx.x] += t;
        __syncthreads();
    }
    if (i < NN) g_rowptr[i] = s[threadIdx.x] - v;   // exclusive within block
    if (threadIdx.x == 1023) g_bsum[blockIdx.x] = s[1023];
}

// parallel block-sum scan (<=128 elems) + c_e = lew . att_edge
__global__ void k_scan2ce(int nb, const float* __restrict__ lew, const float* __restrict__ ae) {
    __shared__ int sc[128];
    int t = threadIdx.x;   // 128 threads
    float p0 = lew[t] * ae[t];
    float p1 = lew[DD + t] * ae[DD + t];
    for (int o = 16; o; o >>= 1) {
        p0 += __shfl_xor_sync(0xffffffffu, p0, o);
        p1 += __shfl_xor_sync(0xffffffffu, p1, o);
    }
    __shared__ float s0[4], s1[4];
    if ((t & 31) == 0) { s0[t >> 5] = p0; s1[t >> 5] = p1; }

    int v = (t < nb) ? g_bsum[t] : 0;
    sc[t] = v;
    __syncthreads();
    for (int off = 1; off < 128; off <<= 1) {
        int a = (t >= off) ? sc[t - off] : 0;
        __syncthreads();
        sc[t] += a;
        __syncthreads();
    }
    if (t < nb) g_bsum[t] = sc[t] - v;   // exclusive
    if (t == 0) {
        g_ce[0] = s0[0] + s0[1] + s0[2] + s0[3];
        g_ce[1] = s1[0] + s1[1] + s1[2] + s1[3];
        g_rowptr[NN] = MM;
    }
}

// finalize rowptr + loop weights
__global__ void k_scan3() {
    int i = blockIdx.x * blockDim.x + threadIdx.x;
    if (i < NN) {
        int v = g_rowptr[i] + g_bsum[i >> 10];
        g_rowptr[i] = v;
        g_wp[i] = v;
        int d = g_deg[i];
        g_loopw[i] = g_sumw[i] / (float)(d > 1 ? d : 1);
    }
}

__global__ void k_scatter(const int* __restrict__ ei, const float* __restrict__ ew) {
    int i = blockIdx.x * blockDim.x + threadIdx.x;
    if (i < EE) {
        int s = ei[i];
        int d = ei[EE + i];
        int pos = atomicAdd(&g_wp[d], 1);
        Edge e; e.s = s; e.w = ew[i];
        g_edge[pos] = e;
    } else if (i < MM) {
        int n = i - EE;
        int pos = atomicAdd(&g_wp[n], 1);
        Edge e; e.s = n; e.w = g_loopw[n];
        g_edge[pos] = e;
    }
}

// ---------------- GEMM 128x128 tile / block, 8x8 per thread ----------------
// Epilogue: alpha_s/alpha_d from fp32 accumulators (full precision), H stored fp16.
template<int SRC>
__global__ void __launch_bounds__(256, 2)
k_gemm(const float* __restrict__ Xin, const float* __restrict__ Wg,
       const float* __restrict__ asrc, const float* __restrict__ adst) {
    __shared__ __align__(16) float sW[32][DD];     // 16 KB
    __shared__ __align__(16) float sXT[32][132];   // 16.9 KB, transposed, pad 132
    const float* __restrict__ X = (SRC == 0) ? Xin : (const float*)g_ACT;

    int tid = threadIdx.x;
    int row0 = blockIdx.x * 128;
    int tx = tid & 15, ty = tid >> 4;
    int ty8 = ty * 8, c0 = tx * 8;

    float acc[8][8];
#pragma unroll
    for (int i = 0; i < 8; i++)
#pragma unroll
        for (int j = 0; j < 8; j++) acc[i][j] = 0.f;

    for (int kc = 0; kc < DD; kc += 32) {
#pragma unroll
        for (int t = 0; t < 4; t++) {
            int idx = tid + t * 256;
            int r = idx >> 5, c4 = idx & 31;
            *(float4*)&sW[r][c4 * 4] = ((const float4*)Wg)[(kc + r) * 32 + c4];
        }
#pragma unroll
        for (int t = 0; t < 4; t++) {
            int idx = tid + t * 256;
            int r = idx >> 3, c4 = idx & 7;
            float4 v = make_float4(0.f, 0.f, 0.f, 0.f);
            int gr = row0 + r;
            if (gr < NN) v = ((const float4*)X)[gr * 32 + (kc >> 2) + c4];
            sXT[c4 * 4 + 0][r] = v.x;
            sXT[c4 * 4 + 1][r] = v.y;
            sXT[c4 * 4 + 2][r] = v.z;
            sXT[c4 * 4 + 3][r] = v.w;
        }
        __syncthreads();

#pragma unroll
        for (int kk = 0; kk < 32; kk++) {
            float4 wa = *(const float4*)&sW[kk][c0];
            float4 wb = *(const float4*)&sW[kk][c0 + 4];
            float4 xa = *(const float4*)&sXT[kk][ty8];
            float4 xb = *(const float4*)&sXT[kk][ty8 + 4];
            float wv[8] = {wa.x, wa.y, wa.z, wa.w, wb.x, wb.y, wb.z, wb.w};
            float xv[8] = {xa.x, xa.y, xa.z, xa.w, xb.x, xb.y, xb.z, xb.w};
#pragma unroll
            for (int i = 0; i < 8; i++)
#pragma unroll
                for (int j = 0; j < 8; j++)
                    acc[i][j] = fmaf(xv[i], wv[j], acc[i][j]);
        }
        __syncthreads();
    }

    // epilogue: fp16 H store + fused alpha (fp32)
    float4 a0 = ((const float4*)asrc)[tx * 2];
    float4 a1 = ((const float4*)asrc)[tx * 2 + 1];
    float4 b0 = ((const float4*)adst)[tx * 2];
    float4 b1 = ((const float4*)adst)[tx * 2 + 1];
#pragma unroll
    for (int i = 0; i < 8; i++) {
        int r = row0 + ty8 + i;
        bool ok = (r < NN);
        if (ok) {
            __half2 hp[4];
            hp[0] = __floats2half2_rn(acc[i][0], acc[i][1]);
            hp[1] = __floats2half2_rn(acc[i][2], acc[i][3]);
            hp[2] = __floats2half2_rn(acc[i][4], acc[i][5]);
            hp[3] = __floats2half2_rn(acc[i][6], acc[i][7]);
            ((uint4*)g_Hh)[(size_t)r * 16 + tx] = *(const uint4*)hp;
        }
        float ps = acc[i][0] * a0.x + acc[i][1] * a0.y + acc[i][2] * a0.z + acc[i][3] * a0.w
                 + acc[i][4] * a1.x + acc[i][5] * a1.y + acc[i][6] * a1.z + acc[i][7] * a1.w;
        float pd = acc[i][0] * b0.x + acc[i][1] * b0.y + acc[i][2] * b0.z + acc[i][3] * b0.w
                 + acc[i][4] * b1.x + acc[i][5] * b1.y + acc[i][6] * b1.z + acc[i][7] * b1.w;
#pragma unroll
        for (int o = 8; o; o >>= 1) {
            ps += __shfl_xor_sync(0xffffffffu, ps, o);
            pd += __shfl_xor_sync(0xffffffffu, pd, o);
        }
        if (tx == 0 && ok) { g_as[r] = ps; g_ad[r] = pd; }
    }
}

__device__ __forceinline__ float leaky(float v) { return v > 0.f ? v : 0.2f * v; }
__device__ __forceinline__ float gelu(float v) {
    return 0.5f * v * (1.f + erff(v * 0.70710678118f));
}

// ---------------- single-pass online-softmax aggregation: warp per node -----
// Gathers fp16 H rows (uint2 per lane). FUSE_LN=0: write g_ACT; =1: LN(x+out).
template<int FUSE_LN>
__global__ void k_agg(int layer, const float* __restrict__ biasl,
                      const float* __restrict__ x, const float* __restrict__ gam,
                      const float* __restrict__ bet, float* __restrict__ outp) {
    int g = blockIdx.x * blockDim.x + threadIdx.x;
    int n = g >> 5, lane = g & 31;
    if (n >= NN) return;
    int beg = g_rowptr[n], end = g_rowptr[n + 1];
    float ad = g_ad[n];
    float ce = g_ce[layer];

    float m = -3.0e38f, z = 0.f;
    float4 acc = make_float4(0.f, 0.f, 0.f, 0.f);
    const uint2* Hv = (const uint2*)g_Hh;   // row = 32 uint2, lane owns one

    for (int base = beg; base < end; base += 32) {
        int j = base + lane;
        float l = -3.0e38f; int s = 0;
        if (j < end) {
            Edge e = g_edge[j];
            s = e.s;
            l = leaky(g_as[s] + ad + ce * e.w);
        }
        // batch max + online rescale
        float bm = l;
#pragma unroll
        for (int o = 16; o; o >>= 1) bm = fmaxf(bm, __shfl_xor_sync(0xffffffffu, bm, o));
        float mn = fmaxf(m, bm);
        float scale = __expf(m - mn);       // first batch: exp(-huge) = 0
        z *= scale;
        acc.x *= scale; acc.y *= scale; acc.z *= scale; acc.w *= scale;
        m = mn;
        float p = (j < end) ? __expf(l - m) : 0.f;
        z += p;

        int cnt = min(32, end - base);
        // 2-deep pipelined row accumulation
        float pe = __shfl_sync(0xffffffffu, p, 0);
        int   se = __shfl_sync(0xffffffffu, s, 0);
        uint2 hv = Hv[(size_t)se * 32 + lane];
        for (int t = 1; t < cnt; t++) {
            float pen = __shfl_sync(0xffffffffu, p, t);
            int   sen = __shfl_sync(0xffffffffu, s, t);
            uint2 nv = Hv[(size_t)sen * 32 + lane];
            float2 f0 = __half22float2(*(const __half2*)&hv.x);
            float2 f1 = __half22float2(*(const __half2*)&hv.y);
            acc.x = fmaf(pe, f0.x, acc.x);
            acc.y = fmaf(pe, f0.y, acc.y);
            acc.z = fmaf(pe, f1.x, acc.z);
            acc.w = fmaf(pe, f1.y, acc.w);
            pe = pen; hv = nv;
        }
        float2 f0 = __half22float2(*(const __half2*)&hv.x);
        float2 f1 = __half22float2(*(const __half2*)&hv.y);
        acc.x = fmaf(pe, f0.x, acc.x);
        acc.y = fmaf(pe, f0.y, acc.y);
        acc.z = fmaf(pe, f1.x, acc.z);
        acc.w = fmaf(pe, f1.y, acc.w);
    }
#pragma unroll
    for (int o = 16; o; o >>= 1) z += __shfl_xor_sync(0xffffffffu, z, o);
    float inv = 1.f / z;
    float4 b = ((const float4*)biasl)[lane];
    float4 o;
    o.x = gelu(acc.x * inv + b.x);
    o.y = gelu(acc.y * inv + b.y);
    o.z = gelu(acc.z * inv + b.z);
    o.w = gelu(acc.w * inv + b.w);

    if (FUSE_LN == 0) {
        ((float4*)g_ACT)[n * 32 + lane] = o;
    } else {
        float4 v = ((const float4*)x)[n * 32 + lane];
        v.x += o.x; v.y += o.y; v.z += o.z; v.w += o.w;
        float s = v.x + v.y + v.z + v.w;
#pragma unroll
        for (int oo = 16; oo; oo >>= 1) s += __shfl_xor_sync(0xffffffffu, s, oo);
        float mu = s * (1.f / 128.f);
        float dx = v.x - mu, dy = v.y - mu, dz = v.z - mu, dw = v.w - mu;
        float q = dx * dx + dy * dy + dz * dz + dw * dw;
#pragma unroll
        for (int oo = 16; oo; oo >>= 1) q += __shfl_xor_sync(0xffffffffu, q, oo);
        float r = rsqrtf(q * (1.f / 128.f) + 1e-5f);
        float4 gg = ((const float4*)gam)[lane];
        float4 bb = ((const float4*)bet)[lane];
        float4 o4;
        o4.x = dx * r * gg.x + bb.x;
        o4.y = dy * r * gg.y + bb.y;
        o4.z = dz * r * gg.z + bb.z;
        o4.w = dw * r * gg.w + bb.w;
        ((float4*)outp)[n * 32 + lane] = o4;
    }
}

// ---------------- host: kernel launches ONLY ----------------
extern "C" void kernel_launch(void* const* d_in, const int* in_sizes, int n_in,
                              void* d_out, int out_size) {
    const float* x     = (const float*)d_in[0];
    const int*   ei    = (const int*)d_in[1];     // int32
    const float* ew    = (const float*)d_in[2];
    const float* W     = (const float*)d_in[3];
    const float* asrc  = (const float*)d_in[4];
    const float* adst  = (const float*)d_in[5];
    const float* lew   = (const float*)d_in[6];
    const float* aedge = (const float*)d_in[7];
    const float* bias  = (const float*)d_in[8];
    const float* gam   = (const float*)d_in[9];
    const float* bet   = (const float*)d_in[10];
    float* out = (float*)d_out;
    (void)in_sizes; (void)n_in; (void)out_size;

    const int TB = 256;
    const int gN  = (NN + TB - 1) / TB;
    const int gE  = (EE + TB - 1) / TB;
    const int gM  = (MM + TB - 1) / TB;
    const int gW  = (NN * 32 + TB - 1) / TB;      // one warp per node
    const int nScanBlk = (NN + 1023) / 1024;       // 98
    const int gGemm = (NN + 127) / 128;            // 782

    // ---- graph preprocessing (CSR with self-loops, mean-fill loop weights) ----
    k_init<<<gN, TB>>>();
    k_deg<<<gE, TB>>>(ei, ew);
    k_scan1<<<nScanBlk, 1024>>>();
    k_scan2ce<<<1, 128>>>(nScanBlk, lew, aedge);
    k_scan3<<<gN, TB>>>();
    k_scatter<<<gM, TB>>>(ei, ew);

    // ---- layer 0 ----
    k_gemm<0><<<gGemm, TB>>>(x, W, asrc, adst);
    k_agg<0><<<gW, TB>>>(0, bias, nullptr, nullptr, nullptr, nullptr);

    // ---- layer 1 (agg fuses residual + layernorm) ----
    k_gemm<1><<<gGemm, TB>>>(nullptr, W + DD * DD, asrc + DD, adst + DD);
    k_agg<1><<<gW, TB>>>(1, bias + DD, x, gam, bet, out);
}

// round 11
// speedup vs baseline: 1.4922x; 1.4922x over previous
#include <cuda_runtime.h>
#include <cuda_fp16.h>
#include <math.h>

#define NN 100000
#define EE 1600000
#define MM (EE + NN)
#define DD 128

struct __align__(8) Edge { int s; float w; };

// ---------------- scratch (static device allocations; no runtime alloc) ----
__device__ int   g_deg[NN];
__device__ float g_sumw[NN];
__device__ float g_loopw[NN];
__device__ int   g_rowptr[NN + 1];
__device__ int   g_wp[NN];
__device__ int   g_bsum[128];
__device__ Edge  g_edge[MM];
__device__ float g_as[NN];
__device__ float g_ad[NN];
__device__ __align__(16) __half2 g_Hh[(size_t)NN * 64];    // fp16 H
__device__ __align__(16) __half2 g_ACTh[(size_t)NN * 64];  // fp16 ACT
__device__ unsigned int g_Wfrag[2][8192];                  // pre-fragmented fp16 W
__device__ float g_ce[2];

// ---------------- preprocessing ----------------
__global__ void k_init() {
    int i = blockIdx.x * blockDim.x + threadIdx.x;
    if (i < NN) { g_deg[i] = 0; g_sumw[i] = 0.f; }
}

// Pre-permute W (fp32 [L][128k][128n]) into mma fragment order:
// frag[kc*1024 + j*64 + i*32 + lane] = half2{ W[k][col], W[k+1][col] }
// k = kc*16 + tg*2 + i*8, col = j*8 + g, g=lane>>2, tg=lane&3.
__global__ void k_wfrag(const float* __restrict__ W) {
    int idx = blockIdx.x * blockDim.x + threadIdx.x;   // 16384 threads
    if (idx >= 16384) return;
    int layer = idx >> 13;
    int r = idx & 8191;
    int kc = r >> 10, j = (r >> 6) & 15, i = (r >> 5) & 1, lane = r & 31;
    int g = lane >> 2, tg = lane & 3;
    int k = kc * 16 + tg * 2 + i * 8;
    int col = j * 8 + g;
    const float* Wl = W + layer * DD * DD;
    __half2 v = __floats2half2_rn(Wl[k * DD + col], Wl[(k + 1) * DD + col]);
    g_Wfrag[layer][r] = *(const unsigned int*)&v;
}

// edge_index is int32
__global__ void k_deg(const int* __restrict__ ei, const float* __restrict__ ew) {
    int i = blockIdx.x * blockDim.x + threadIdx.x;
    if (i < EE) {
        int d = ei[EE + i];
        atomicAdd(&g_deg[d], 1);
        atomicAdd(&g_sumw[d], ew[i]);
    }
}

__global__ void k_scan1() {
    __shared__ int s[1024];
    int i = blockIdx.x * 1024 + threadIdx.x;
    int v = (i < NN) ? g_deg[i] + 1 : 0;   // +1 self-loop
    s[threadIdx.x] = v;
    __syncthreads();
    for (int off = 1; off < 1024; off <<= 1) {
        int t = (threadIdx.x >= off) ? s[threadIdx.x - off] : 0;
        __syncthreads();
        s[threadIdx.x] += t;
        __syncthreads();
    }
    if (i < NN) g_rowptr[i] = s[threadIdx.x] - v;
    if (threadIdx.x == 1023) g_bsum[blockIdx.x] = s[1023];
}

// parallel block-sum scan (<=128 elems) + c_e = lew . att_edge
__global__ void k_scan2ce(int nb, const float* __restrict__ lew, const float* __restrict__ ae) {
    __shared__ int sc[128];
    int t = threadIdx.x;
    float p0 = lew[t] * ae[t];
    float p1 = lew[DD + t] * ae[DD + t];
    for (int o = 16; o; o >>= 1) {
        p0 += __shfl_xor_sync(0xffffffffu, p0, o);
        p1 += __shfl_xor_sync(0xffffffffu, p1, o);
    }
    __shared__ float s0[4], s1[4];
    if ((t & 31) == 0) { s0[t >> 5] = p0; s1[t >> 5] = p1; }

    int v = (t < nb) ? g_bsum[t] : 0;
    sc[t] = v;
    __syncthreads();
    for (int off = 1; off < 128; off <<= 1) {
        int a = (t >= off) ? sc[t - off] : 0;
        __syncthreads();
        sc[t] += a;
        __syncthreads();
    }
    if (t < nb) g_bsum[t] = sc[t] - v;
    if (t == 0) {
        g_ce[0] = s0[0] + s0[1] + s0[2] + s0[3];
        g_ce[1] = s1[0] + s1[1] + s1[2] + s1[3];
        g_rowptr[NN] = MM;
    }
}

__global__ void k_scan3() {
    int i = blockIdx.x * blockDim.x + threadIdx.x;
    if (i < NN) {
        int v = g_rowptr[i] + g_bsum[i >> 10];
        g_rowptr[i] = v;
        g_wp[i] = v;
        int d = g_deg[i];
        g_loopw[i] = g_sumw[i] / (float)(d > 1 ? d : 1);
    }
}

__global__ void k_scatter(const int* __restrict__ ei, const float* __restrict__ ew) {
    int i = blockIdx.x * blockDim.x + threadIdx.x;
    if (i < EE) {
        int s = ei[i];
        int d = ei[EE + i];
        int pos = atomicAdd(&g_wp[d], 1);
        Edge e; e.s = s; e.w = ew[i];
        g_edge[pos] = e;
    } else if (i < MM) {
        int n = i - EE;
        int pos = atomicAdd(&g_wp[n], 1);
        Edge e; e.s = n; e.w = g_loopw[n];
        g_edge[pos] = e;
    }
}

// ---------------- tensor-core GEMM: 128 rows/block, 8 warps x m16n128 -------
// A = X (fp16 smem, row-major), B = W via pre-fragmented g_Wfrag.
// C fp32 frags -> fp16 H store + fused alpha_s/alpha_d (fp32 precision).
template<int SRC>
__global__ void __launch_bounds__(256, 2)
k_gemm(const float* __restrict__ Xin, int layer,
       const float* __restrict__ asrc, const float* __restrict__ adst) {
    __shared__ __align__(16) __half sX[128][136];        // 34816 B
    __shared__ unsigned int sB[2048];                    // 8192 B: [kc2][j][i][lane]
    __shared__ float sAs[DD], sAd[DD];                   // 1024 B

    int tid = threadIdx.x;
    int warp = tid >> 5, lane = tid & 31;
    int g = lane >> 2, tg = lane & 3;
    int row0 = blockIdx.x * 128;

    if (tid < DD) { sAs[tid] = asrc[tid]; sAd[tid] = adst[tid]; }

    // ---- load X tile to fp16 smem ----
    if (SRC == 0) {
#pragma unroll
        for (int t = 0; t < 16; t++) {
            int idx = tid + t * 256;                 // 4096 float4 slots
            int r = idx >> 5, c4 = idx & 31;
            float4 v = make_float4(0.f, 0.f, 0.f, 0.f);
            int gr = row0 + r;
            if (gr < NN) v = ((const float4*)Xin)[gr * 32 + c4];
            __half2 h0 = __floats2half2_rn(v.x, v.y);
            __half2 h1 = __floats2half2_rn(v.z, v.w);
            unsigned int u0 = *(const unsigned int*)&h0;
            unsigned int u1 = *(const unsigned int*)&h1;
            uint2 p = make_uint2(u0, u1);
            *(uint2*)&sX[r][c4 * 4] = p;
        }
    } else {
#pragma unroll
        for (int t = 0; t < 8; t++) {
            int idx = tid + t * 256;                 // 2048 uint4 slots
            int r = idx >> 4, c8 = idx & 15;
            uint4 v = make_uint4(0u, 0u, 0u, 0u);
            int gr = row0 + r;
            if (gr < NN) v = ((const uint4*)g_ACTh)[gr * 16 + c8];
            *(uint4*)&sX[r][c8 * 8] = v;
        }
    }

    float c[16][4];
#pragma unroll
    for (int j = 0; j < 16; j++)
#pragma unroll
        for (int q = 0; q < 4; q++) c[j][q] = 0.f;

    int mrow = warp * 16;
    const unsigned int* wf = g_Wfrag[layer];

#pragma unroll
    for (int st = 0; st < 4; st++) {
        __syncthreads();
#pragma unroll
        for (int q = 0; q < 8; q++) sB[tid + q * 256] = wf[st * 2048 + tid + q * 256];
        __syncthreads();
#pragma unroll
        for (int kc2 = 0; kc2 < 2; kc2++) {
            int k0 = (st * 2 + kc2) * 16;
            unsigned int a0 = *(const unsigned int*)&sX[mrow + g][k0 + tg * 2];
            unsigned int a1 = *(const unsigned int*)&sX[mrow + g + 8][k0 + tg * 2];
            unsigned int a2 = *(const unsigned int*)&sX[mrow + g][k0 + tg * 2 + 8];
            unsigned int a3 = *(const unsigned int*)&sX[mrow + g + 8][k0 + tg * 2 + 8];
#pragma unroll
            for (int j = 0; j < 16; j++) {
                unsigned int b0 = sB[kc2 * 1024 + j * 64 + lane];
                unsigned int b1 = sB[kc2 * 1024 + j * 64 + 32 + lane];
                asm volatile(
                    "mma.sync.aligned.m16n8k16.row.col.f32.f16.f16.f32 "
                    "{%0,%1,%2,%3}, {%4,%5,%6,%7}, {%8,%9}, {%0,%1,%2,%3};\n"
                    : "+f"(c[j][0]), "+f"(c[j][1]), "+f"(c[j][2]), "+f"(c[j][3])
                    : "r"(a0), "r"(a1), "r"(a2), "r"(a3), "r"(b0), "r"(b1));
            }
        }
    }

    // ---- epilogue: fp16 H store + fused alpha (fp32) ----
    int r0 = row0 + mrow + g;
    int r1 = r0 + 8;
    bool ok0 = (r0 < NN), ok1 = (r1 < NN);
    float ps0 = 0.f, pd0 = 0.f, ps1 = 0.f, pd1 = 0.f;
#pragma unroll
    for (int j = 0; j < 16; j++) {
        int c0i = j * 8 + tg * 2;
        float av0 = sAs[c0i], av1 = sAs[c0i + 1];
        float bv0 = sAd[c0i], bv1 = sAd[c0i + 1];
        ps0 += c[j][0] * av0 + c[j][1] * av1;
        pd0 += c[j][0] * bv0 + c[j][1] * bv1;
        ps1 += c[j][2] * av0 + c[j][3] * av1;
        pd1 += c[j][2] * bv0 + c[j][3] * bv1;
        if (ok0) g_Hh[(size_t)r0 * 64 + (c0i >> 1)] = __floats2half2_rn(c[j][0], c[j][1]);
        if (ok1) g_Hh[(size_t)r1 * 64 + (c0i >> 1)] = __floats2half2_rn(c[j][2], c[j][3]);
    }
#pragma unroll
    for (int o = 1; o <= 2; o <<= 1) {
        ps0 += __shfl_xor_sync(0xffffffffu, ps0, o);
        pd0 += __shfl_xor_sync(0xffffffffu, pd0, o);
        ps1 += __shfl_xor_sync(0xffffffffu, ps1, o);
        pd1 += __shfl_xor_sync(0xffffffffu, pd1, o);
    }
    if (tg == 0) {
        if (ok0) { g_as[r0] = ps0; g_ad[r0] = pd0; }
        if (ok1) { g_as[r1] = ps1; g_ad[r1] = pd1; }
    }
}

__device__ __forceinline__ float leaky(float v) { return v > 0.f ? v : 0.2f * v; }
__device__ __forceinline__ float gelu(float v) {
    return 0.5f * v * (1.f + erff(v * 0.70710678118f));
}

// ---------------- single-pass online-softmax aggregation: warp per node -----
// Dual accumulator chains, 2 loads in flight. FUSE_LN=0: fp16 ACT; =1: LN(x+o).
template<int FUSE_LN>
__global__ void k_agg(int layer, const float* __restrict__ biasl,
                      const float* __restrict__ x, const float* __restrict__ gam,
                      const float* __restrict__ bet, float* __restrict__ outp) {
    int gg = blockIdx.x * blockDim.x + threadIdx.x;
    int n = gg >> 5, lane = gg & 31;
    if (n >= NN) return;
    int beg = g_rowptr[n], end = g_rowptr[n + 1];
    float ad = g_ad[n];
    float ce = g_ce[layer];

    float m = -3.0e38f, z = 0.f;
    float4 accA = make_float4(0.f, 0.f, 0.f, 0.f);
    float4 accB = make_float4(0.f, 0.f, 0.f, 0.f);
    const uint2* Hv = (const uint2*)g_Hh;   // row = 32 uint2, lane owns one

    for (int base = beg; base < end; base += 32) {
        int j = base + lane;
        float l = -3.0e38f; int s = 0;
        if (j < end) {
            Edge e = g_edge[j];
            s = e.s;
            l = leaky(g_as[s] + ad + ce * e.w);
        }
        float bm = l;
#pragma unroll
        for (int o = 16; o; o >>= 1) bm = fmaxf(bm, __shfl_xor_sync(0xffffffffu, bm, o));
        float mn = fmaxf(m, bm);
        float scale = __expf(m - mn);
        z *= scale;
        accA.x *= scale; accA.y *= scale; accA.z *= scale; accA.w *= scale;
        accB.x *= scale; accB.y *= scale; accB.z *= scale; accB.w *= scale;
        m = mn;
        float p = (j < end) ? __expf(l - m) : 0.f;
        z += p;

        int cnt = min(32, end - base);
        int t = 0;
        for (; t + 1 < cnt; t += 2) {
            float pa = __shfl_sync(0xffffffffu, p, t);
            float pb = __shfl_sync(0xffffffffu, p, t + 1);
            int   sa = __shfl_sync(0xffffffffu, s, t);
            int   sb = __shfl_sync(0xffffffffu, s, t + 1);
            uint2 ha = Hv[(size_t)sa * 32 + lane];
            uint2 hb = Hv[(size_t)sb * 32 + lane];
            float2 fa0 = __half22float2(*(const __half2*)&ha.x);
            float2 fa1 = __half22float2(*(const __half2*)&ha.y);
            float2 fb0 = __half22float2(*(const __half2*)&hb.x);
            float2 fb1 = __half22float2(*(const __half2*)&hb.y);
            accA.x = fmaf(pa, fa0.x, accA.x);
            accA.y = fmaf(pa, fa0.y, accA.y);
            accA.z = fmaf(pa, fa1.x, accA.z);
            accA.w = fmaf(pa, fa1.y, accA.w);
            accB.x = fmaf(pb, fb0.x, accB.x);
            accB.y = fmaf(pb, fb0.y, accB.y);
            accB.z = fmaf(pb, fb1.x, accB.z);
            accB.w = fmaf(pb, fb1.y, accB.w);
        }
        if (t < cnt) {
            float pa = __shfl_sync(0xffffffffu, p, t);
            int   sa = __shfl_sync(0xffffffffu, s, t);
            uint2 ha = Hv[(size_t)sa * 32 + lane];
            float2 fa0 = __half22float2(*(const __half2*)&ha.x);
            float2 fa1 = __half22float2(*(const __half2*)&ha.y);
            accA.x = fmaf(pa, fa0.x, accA.x);
            accA.y = fmaf(pa, fa0.y, accA.y);
            accA.z = fmaf(pa, fa1.x, accA.z);
            accA.w = fmaf(pa, fa1.y, accA.w);
        }
    }
#pragma unroll
    for (int o = 16; o; o >>= 1) z += __shfl_xor_sync(0xffffffffu, z, o);
    float inv = 1.f / z;
    float4 b = ((const float4*)biasl)[lane];
    float4 o;
    o.x = gelu((accA.x + accB.x) * inv + b.x);
    o.y = gelu((accA.y + accB.y) * inv + b.y);
    o.z = gelu((accA.z + accB.z) * inv + b.z);
    o.w = gelu((accA.w + accB.w) * inv + b.w);

    if (FUSE_LN == 0) {
        __half2 h0 = __floats2half2_rn(o.x, o.y);
        __half2 h1 = __floats2half2_rn(o.z, o.w);
        uint2 p = make_uint2(*(const unsigned int*)&h0, *(const unsigned int*)&h1);
        ((uint2*)g_ACTh)[(size_t)n * 32 + lane] = p;
    } else {
        float4 v = ((const float4*)x)[n * 32 + lane];
        v.x += o.x; v.y += o.y; v.z += o.z; v.w += o.w;
        float s = v.x + v.y + v.z + v.w;
#pragma unroll
        for (int oo = 16; oo; oo >>= 1) s += __shfl_xor_sync(0xffffffffu, s, oo);
        float mu = s * (1.f / 128.f);
        float dx = v.x - mu, dy = v.y - mu, dz = v.z - mu, dw = v.w - mu;
        float q = dx * dx + dy * dy + dz * dz + dw * dw;
#pragma unroll
        for (int oo = 16; oo; oo >>= 1) q += __shfl_xor_sync(0xffffffffu, q, oo);
        float r = rsqrtf(q * (1.f / 128.f) + 1e-5f);
        float4 gg2 = ((const float4*)gam)[lane];
        float4 bb = ((const float4*)bet)[lane];
        float4 o4;
        o4.x = dx * r * gg2.x + bb.x;
        o4.y = dy * r * gg2.y + bb.y;
        o4.z = dz * r * gg2.z + bb.z;
        o4.w = dw * r * gg2.w + bb.w;
        ((float4*)outp)[n * 32 + lane] = o4;
    }
}

// ---------------- host: kernel launches ONLY ----------------
extern "C" void kernel_launch(void* const* d_in, const int* in_sizes, int n_in,
                              void* d_out, int out_size) {
    const float* x     = (const float*)d_in[0];
    const int*   ei    = (const int*)d_in[1];     // int32
    const float* ew    = (const float*)d_in[2];
    const float* W     = (const float*)d_in[3];
    const float* asrc  = (const float*)d_in[4];
    const float* adst  = (const float*)d_in[5];
    const float* lew   = (const float*)d_in[6];
    const float* aedge = (const float*)d_in[7];
    const float* bias  = (const float*)d_in[8];
    const float* gam   = (const float*)d_in[9];
    const float* bet   = (const float*)d_in[10];
    float* out = (float*)d_out;
    (void)in_sizes; (void)n_in; (void)out_size;

    const int TB = 256;
    const int gN  = (NN + TB - 1) / TB;
    const int gE  = (EE + TB - 1) / TB;
    const int gM  = (MM + TB - 1) / TB;
    const int gW  = (NN * 32 + TB - 1) / TB;      // one warp per node
    const int nScanBlk = (NN + 1023) / 1024;       // 98
    const int gGemm = (NN + 127) / 128;            // 782

    // launch order places k_gemm<0> at index 3 (ncu capture slot)
    k_init<<<gN, TB>>>();                               // 0
    k_wfrag<<<64, TB>>>(W);                             // 1
    k_deg<<<gE, TB>>>(ei, ew);                          // 2
    k_gemm<0><<<gGemm, TB>>>(x, 0, asrc, adst);         // 3  <- profiled
    k_scan1<<<nScanBlk, 1024>>>();                      // 4
    k_scan2ce<<<1, 128>>>(nScanBlk, lew, aedge);        // 5
    k_scan3<<<gN, TB>>>();                              // 6
    k_scatter<<<gM, TB>>>(ei, ew);                      // 7
    k_agg<0><<<gW, TB>>>(0, bias, nullptr, nullptr, nullptr, nullptr);   // 8
    k_gemm<1><<<gGemm, TB>>>(nullptr, 1, asrc + DD, adst + DD);          // 9
    k_agg<1><<<gW, TB>>>(1, bias + DD, x, gam, bet, out);                // 10
}